// round 1
// baseline (speedup 1.0000x reference)
#include <cuda_runtime.h>
#include <cuda_bf16.h>
#include <math_constants.h>

// Problem constants (fixed by the reference)
#define NNODES 8192
#define NB     64
#define E0     32768
#define DIN1   32
#define DH     64
#define BOND   5
// P layout: [N][6][64]  (k=0..4 bond projections, k=5 bias projection)
#define PSTRIDE (6*DH)   // 384

// Scratch (allocation-free rule: __device__ globals)
__device__ float g_P[NNODES * PSTRIDE];   // 12.6 MB, reused for layer 1 and 2
__device__ float g_agg[NNODES * DH];      // 2 MB, reused for layer 1 and 2

// ---------------------------------------------------------------------------
// Projection: P[n, k*64+o] = sum_i x[n,i] * W_k[i,o]
//   W_k[i,o] = eW[k, i*64+o] for k<5, eb[i*64+o] for k==5
// blockDim = 384 (thread owns one (k,o) column), 32 nodes/block in groups of 4
// ---------------------------------------------------------------------------
template<int DIN, int RELU_IN>
__global__ void __launch_bounds__(384) proj_kernel(
    const float* __restrict__ x,    // [N, DIN]
    const float* __restrict__ eW,   // [5, DIN*64]
    const float* __restrict__ eb,   // [DIN*64]
    float* __restrict__ P)          // [N, 384]
{
    const int tid = threadIdx.x;
    const int k = tid >> 6;
    const int o = tid & 63;

    // weight column into registers (coalesced across o)
    float w[DIN];
    const float* wsrc = (k < 5) ? (eW + k * DIN * 64) : eb;
    #pragma unroll
    for (int i = 0; i < DIN; i++) w[i] = wsrc[i * 64 + o];

    __shared__ float xs[4][DIN];

    const int node0 = blockIdx.x * 32;
    #pragma unroll 1
    for (int g = 0; g < 8; g++) {
        const int nbase = node0 + g * 4;
        // cooperative coalesced load of 4 node rows
        for (int idx = tid; idx < 4 * DIN; idx += 384) {
            float v = x[(nbase + idx / DIN) * DIN + (idx % DIN)];
            if (RELU_IN) v = fmaxf(v, 0.0f);
            xs[idx / DIN][idx % DIN] = v;
        }
        __syncthreads();

        float a0 = 0.f, a1 = 0.f, a2 = 0.f, a3 = 0.f;
        #pragma unroll
        for (int i = 0; i < DIN; i++) {
            const float wi = w[i];
            a0 = fmaf(wi, xs[0][i], a0);
            a1 = fmaf(wi, xs[1][i], a1);
            a2 = fmaf(wi, xs[2][i], a2);
            a3 = fmaf(wi, xs[3][i], a3);
        }
        P[(nbase + 0) * PSTRIDE + tid] = a0;
        P[(nbase + 1) * PSTRIDE + tid] = a1;
        P[(nbase + 2) * PSTRIDE + tid] = a2;
        P[(nbase + 3) * PSTRIDE + tid] = a3;
        __syncthreads();
    }
}

// ---------------------------------------------------------------------------
// agg init: bias + self-loop (self-loop has ef=0 -> message = P_b[n])
// ---------------------------------------------------------------------------
__global__ void init_agg_kernel(const float* __restrict__ P,
                                const float* __restrict__ bias,
                                float* __restrict__ agg)
{
    int idx = blockIdx.x * blockDim.x + threadIdx.x;
    if (idx >= NNODES * DH) return;
    const int n = idx >> 6;
    const int o = idx & 63;
    agg[idx] = bias[o] + P[n * PSTRIDE + 5 * 64 + o];
}

// ---------------------------------------------------------------------------
// Edge scatter: one warp per edge; lane handles output pair (2*lane, 2*lane+1)
//   m = P_b[src] + sum_k ef[e,k] * P_k[src];  atomicAdd into agg[dst]
// ---------------------------------------------------------------------------
__global__ void __launch_bounds__(256) edge_kernel(
    const float* __restrict__ P,
    const float* __restrict__ ef,   // [E0, 5]
    const int*   __restrict__ src,
    const int*   __restrict__ dst,
    float* __restrict__ agg)
{
    const int e = (blockIdx.x * blockDim.x + threadIdx.x) >> 5;
    if (e >= E0) return;
    const int lane = threadIdx.x & 31;

    const int s = src[e];
    const int d = dst[e];
    const float f0 = ef[e * BOND + 0];
    const float f1 = ef[e * BOND + 1];
    const float f2 = ef[e * BOND + 2];
    const float f3 = ef[e * BOND + 3];
    const float f4 = ef[e * BOND + 4];

    const float2* p = reinterpret_cast<const float2*>(P + (size_t)s * PSTRIDE);
    const float2 pb = p[5 * 32 + lane];
    const float2 p0 = p[0 * 32 + lane];
    const float2 p1 = p[1 * 32 + lane];
    const float2 p2 = p[2 * 32 + lane];
    const float2 p3 = p[3 * 32 + lane];
    const float2 p4 = p[4 * 32 + lane];

    float mx = pb.x;
    mx = fmaf(f0, p0.x, mx); mx = fmaf(f1, p1.x, mx); mx = fmaf(f2, p2.x, mx);
    mx = fmaf(f3, p3.x, mx); mx = fmaf(f4, p4.x, mx);
    float my = pb.y;
    my = fmaf(f0, p0.y, my); my = fmaf(f1, p1.y, my); my = fmaf(f2, p2.y, my);
    my = fmaf(f3, p3.y, my); my = fmaf(f4, p4.y, my);

    float* a = agg + (size_t)d * DH + 2 * lane;
    atomicAdd(a,     mx);
    atomicAdd(a + 1, my);
}

// ---------------------------------------------------------------------------
// Pooling + timestep conditioning + final activation
// one block per graph (128 contiguous nodes), 128 threads
// ---------------------------------------------------------------------------
__global__ void __launch_bounds__(128) pool_kernel(
    const float* __restrict__ agg,   // [N, 64] (pre-relu)
    const float* __restrict__ wsW,   // [64]
    const float* __restrict__ wsb,   // [1]
    const float* __restrict__ tstep, // [B]
    float* __restrict__ out)         // [B, 128]
{
    __shared__ float hs[128][65];
    __shared__ float wv[128];
    __shared__ float gsum[64];
    __shared__ float gmax[64];

    const int g = blockIdx.x;
    const int t = threadIdx.x;
    const int base = g * 128;

    // coalesced load + relu
    for (int idx = t; idx < 128 * 64; idx += 128) {
        hs[idx >> 6][idx & 63] = fmaxf(agg[base * 64 + idx], 0.0f);
    }
    __syncthreads();

    // node weight w = sigmoid(h @ wsW + wsb)
    float acc = 0.f;
    #pragma unroll
    for (int c = 0; c < 64; c++) acc = fmaf(hs[t][c], wsW[c], acc);
    wv[t] = 1.0f / (1.0f + expf(-(acc + wsb[0])));
    __syncthreads();

    if (t < 64) {
        float s = 0.f, m = -CUDART_INF_F;
        #pragma unroll 4
        for (int r = 0; r < 128; r++) {
            const float h = hs[r][t];
            s = fmaf(h, wv[r], s);
            m = fmaxf(m, h);
        }
        gsum[t] = s;
        gmax[t] = m;
    }
    __syncthreads();

    const float ts = tstep[g];
    float v;
    if (t < 64) {
        const float inv = expf(-logf(10000.0f) * (2.0f * t) / 128.0f);
        v = gsum[t] + sinf(ts * inv);
    } else {
        const int j = t - 64;
        const float inv = expf(-logf(10000.0f) * (2.0f * j) / 128.0f);
        v = gmax[j] + cosf(ts * inv);
    }
    out[g * 128 + t] = tanhf(fmaxf(v, 0.0f));
}

// ---------------------------------------------------------------------------
extern "C" void kernel_launch(void* const* d_in, const int* in_sizes, int n_in,
                              void* d_out, int out_size)
{
    const float* node_feats = (const float*)d_in[0];   // [8192, 32]
    const float* edge_feats = (const float*)d_in[1];   // [32768, 5]
    const int*   src        = (const int*)  d_in[2];   // [32768]
    const int*   dst        = (const int*)  d_in[3];   // [32768]
    // d_in[4] = graph_ids (contiguous: g = n/128), unused
    const float* timestep   = (const float*)d_in[5];   // [64, 1]
    const float* edge_W1    = (const float*)d_in[6];   // [5, 2048]
    const float* edge_b1    = (const float*)d_in[7];   // [2048]
    const float* bias1      = (const float*)d_in[8];   // [64]
    const float* edge_W2    = (const float*)d_in[9];   // [5, 4096]
    const float* edge_b2    = (const float*)d_in[10];  // [4096]
    const float* bias2      = (const float*)d_in[11];  // [64]
    const float* ws_W       = (const float*)d_in[12];  // [64]
    const float* ws_b       = (const float*)d_in[13];  // [1]
    float* out = (float*)d_out;                        // [64, 128]

    float* P   = nullptr;
    float* agg = nullptr;
    cudaGetSymbolAddress((void**)&P,   g_P);
    cudaGetSymbolAddress((void**)&agg, g_agg);

    const int edge_blocks = (E0 * 32) / 256;           // 4096
    const int init_blocks = (NNODES * DH + 255) / 256; // 2048

    // Layer 1
    proj_kernel<DIN1, 0><<<NNODES / 32, 384>>>(node_feats, edge_W1, edge_b1, P);
    init_agg_kernel<<<init_blocks, 256>>>(P, bias1, agg);
    edge_kernel<<<edge_blocks, 256>>>(P, edge_feats, src, dst, agg);

    // Layer 2 (relu applied to layer-1 agg on load)
    proj_kernel<DH, 1><<<NNODES / 32, 384>>>(agg, edge_W2, edge_b2, P);
    init_agg_kernel<<<init_blocks, 256>>>(P, bias2, agg);
    edge_kernel<<<edge_blocks, 256>>>(P, edge_feats, src, dst, agg);

    // Pool + timestep + tanh(relu(.))
    pool_kernel<<<NB, 128>>>(agg, ws_W, ws_b, timestep, out);
}

// round 4
// speedup vs baseline: 1.2159x; 1.2159x over previous
#include <cuda_runtime.h>
#include <cuda_bf16.h>
#include <math_constants.h>

// Problem constants (fixed by the reference)
#define NNODES 8192
#define NB     64
#define E0     32768
#define DIN1   32
#define DH     64
#define BOND   5
// P layout: [N][6][64]  (k=0..4 bond projections, k=5 bias projection)
#define PSTRIDE (6*DH)   // 384

// Scratch (allocation-free rule: __device__ globals)
__device__ float g_P[NNODES * PSTRIDE];   // 12.6 MB, reused for layer 1 and 2
__device__ float g_agg[NNODES * DH];      // 2 MB, reused for layer 1 and 2

// Packed f32x2 FMA (Blackwell): acc.{lo,hi} += a.{lo,hi} * b.{lo,hi}
__device__ __forceinline__ void ffma2(unsigned long long& acc,
                                      unsigned long long a,
                                      unsigned long long b) {
    asm("fma.rn.f32x2 %0, %1, %2, %0;" : "+l"(acc) : "l"(a), "l"(b));
}
__device__ __forceinline__ unsigned long long pack2(float a, float b) {
    unsigned long long r;
    asm("mov.b64 %0, {%1, %2};" : "=l"(r) : "f"(a), "f"(b));
    return r;
}
__device__ __forceinline__ float unpack_sum(unsigned long long v) {
    float lo, hi;
    asm("mov.b64 {%0, %1}, %2;" : "=f"(lo), "=f"(hi) : "l"(v));
    return lo + hi;
}

// ---------------------------------------------------------------------------
// Projection: P[n, k*64+o] = sum_i x[n,i] * W_k[i,o]
//   W_k[i,o] = eW[k, i*64+o] for k<5, eb[i*64+o] for k==5
// Also fuses agg init: agg[n,o] = bias[o] + P_5[n,o]  (self-loop msg + bias)
// blockDim = 384 (thread owns one (k,o) column), 8 nodes per group,
// grid-stride over 1024 groups. Even/odd input dims packed into f32x2 lanes.
// ---------------------------------------------------------------------------
template<int DIN, int RELU_IN>
__global__ void __launch_bounds__(384) proj_kernel(
    const float* __restrict__ x,     // [N, DIN]
    const float* __restrict__ eW,    // [5, DIN*64]
    const float* __restrict__ eb,    // [DIN*64]
    const float* __restrict__ bias,  // [64]
    float* __restrict__ P,           // [N, 384]
    float* __restrict__ agg)         // [N, 64]
{
    const int tid = threadIdx.x;
    const int k = tid >> 6;
    const int o = tid & 63;

    // pre-packed weight column: wp[c] = (w[2c], w[2c+1])
    unsigned long long wp[DIN / 2];
    const float* wsrc = (k < 5) ? (eW + k * DIN * 64) : eb;
    #pragma unroll
    for (int c = 0; c < DIN / 2; c++)
        wp[c] = pack2(wsrc[(2 * c) * 64 + o], wsrc[(2 * c + 1) * 64 + o]);

    const float bo = bias[o];

    // 8 node rows of DIN floats (plain row layout; reads are warp-broadcast)
    __shared__ ulonglong2 xs[8][DIN / 4];

    for (int g = blockIdx.x; g < NNODES / 8; g += gridDim.x) {
        const int nbase = g * 8;

        // cooperative vectorized load (nodes are contiguous in memory)
        const float4* xg = reinterpret_cast<const float4*>(x + (size_t)nbase * DIN);
        if (tid < 2 * DIN) {
            float4 v = xg[tid];
            if (RELU_IN) {
                v.x = fmaxf(v.x, 0.f); v.y = fmaxf(v.y, 0.f);
                v.z = fmaxf(v.z, 0.f); v.w = fmaxf(v.w, 0.f);
            }
            reinterpret_cast<float4*>(xs)[tid] = v;
        }
        __syncthreads();

        unsigned long long acc[8];
        #pragma unroll
        for (int j = 0; j < 8; j++) acc[j] = 0ull;  // (0.f, 0.f)

        #pragma unroll
        for (int c = 0; c < DIN / 4; c++) {
            #pragma unroll
            for (int j = 0; j < 8; j++) {
                ulonglong2 v = xs[j][c];           // LDS.128 broadcast
                ffma2(acc[j], wp[2 * c],     v.x); // dims 4c, 4c+1
                ffma2(acc[j], wp[2 * c + 1], v.y); // dims 4c+2, 4c+3
            }
        }
        __syncthreads();

        #pragma unroll
        for (int j = 0; j < 8; j++) {
            const float r = unpack_sum(acc[j]);
            P[(size_t)(nbase + j) * PSTRIDE + tid] = r;
            if (k == 5)  // warp-uniform branch: fused agg init (bias + self-loop)
                agg[(size_t)(nbase + j) * DH + o] = bo + r;
        }
    }
}

// ---------------------------------------------------------------------------
// Edge scatter: one warp per edge; lane handles output pair (2*lane, 2*lane+1)
//   m = P_b[src] + sum_k ef[e,k] * P_k[src];  atomicAdd into agg[dst]
// ---------------------------------------------------------------------------
__global__ void __launch_bounds__(256) edge_kernel(
    const float* __restrict__ P,
    const float* __restrict__ ef,   // [E0, 5]
    const int*   __restrict__ src,
    const int*   __restrict__ dst,
    float* __restrict__ agg)
{
    const int e = (blockIdx.x * blockDim.x + threadIdx.x) >> 5;
    if (e >= E0) return;
    const int lane = threadIdx.x & 31;

    const int s = src[e];
    const int d = dst[e];
    const float f0 = ef[e * BOND + 0];
    const float f1 = ef[e * BOND + 1];
    const float f2 = ef[e * BOND + 2];
    const float f3 = ef[e * BOND + 3];
    const float f4 = ef[e * BOND + 4];

    const float2* p = reinterpret_cast<const float2*>(P + (size_t)s * PSTRIDE);
    const float2 pb = p[5 * 32 + lane];
    const float2 p0 = p[0 * 32 + lane];
    const float2 p1 = p[1 * 32 + lane];
    const float2 p2 = p[2 * 32 + lane];
    const float2 p3 = p[3 * 32 + lane];
    const float2 p4 = p[4 * 32 + lane];

    float mx = pb.x;
    mx = fmaf(f0, p0.x, mx); mx = fmaf(f1, p1.x, mx); mx = fmaf(f2, p2.x, mx);
    mx = fmaf(f3, p3.x, mx); mx = fmaf(f4, p4.x, mx);
    float my = pb.y;
    my = fmaf(f0, p0.y, my); my = fmaf(f1, p1.y, my); my = fmaf(f2, p2.y, my);
    my = fmaf(f3, p3.y, my); my = fmaf(f4, p4.y, my);

    float* a = agg + (size_t)d * DH + 2 * lane;
    atomicAdd(a,     mx);
    atomicAdd(a + 1, my);
}

// ---------------------------------------------------------------------------
// Pooling + timestep conditioning + final activation
// one block per graph (128 contiguous nodes), 128 threads
// ---------------------------------------------------------------------------
__global__ void __launch_bounds__(128) pool_kernel(
    const float* __restrict__ agg,   // [N, 64] (pre-relu)
    const float* __restrict__ wsW,   // [64]
    const float* __restrict__ wsb,   // [1]
    const float* __restrict__ tstep, // [B]
    float* __restrict__ out)         // [B, 128]
{
    __shared__ float hs[128][65];
    __shared__ float wv[128];
    __shared__ float gsum[64];
    __shared__ float gmax[64];

    const int g = blockIdx.x;
    const int t = threadIdx.x;
    const int base = g * 128;

    // coalesced load + relu
    for (int idx = t; idx < 128 * 64; idx += 128) {
        hs[idx >> 6][idx & 63] = fmaxf(agg[base * 64 + idx], 0.0f);
    }
    __syncthreads();

    // node weight w = sigmoid(h @ wsW + wsb)
    float acc = 0.f;
    #pragma unroll
    for (int c = 0; c < 64; c++) acc = fmaf(hs[t][c], wsW[c], acc);
    wv[t] = 1.0f / (1.0f + expf(-(acc + wsb[0])));
    __syncthreads();

    if (t < 64) {
        float s = 0.f, m = -CUDART_INF_F;
        #pragma unroll 4
        for (int r = 0; r < 128; r++) {
            const float h = hs[r][t];
            s = fmaf(h, wv[r], s);
            m = fmaxf(m, h);
        }
        gsum[t] = s;
        gmax[t] = m;
    }
    __syncthreads();

    const float ts = tstep[g];
    float v;
    if (t < 64) {
        const float inv = expf(-logf(10000.0f) * (2.0f * t) / 128.0f);
        v = gsum[t] + sinf(ts * inv);
    } else {
        const int j = t - 64;
        const float inv = expf(-logf(10000.0f) * (2.0f * j) / 128.0f);
        v = gmax[j] + cosf(ts * inv);
    }
    out[g * 128 + t] = tanhf(fmaxf(v, 0.0f));
}

// ---------------------------------------------------------------------------
extern "C" void kernel_launch(void* const* d_in, const int* in_sizes, int n_in,
                              void* d_out, int out_size)
{
    const float* node_feats = (const float*)d_in[0];   // [8192, 32]
    const float* edge_feats = (const float*)d_in[1];   // [32768, 5]
    const int*   src        = (const int*)  d_in[2];   // [32768]
    const int*   dst        = (const int*)  d_in[3];   // [32768]
    // d_in[4] = graph_ids (contiguous: g = n/128), unused
    const float* timestep   = (const float*)d_in[5];   // [64, 1]
    const float* edge_W1    = (const float*)d_in[6];   // [5, 2048]
    const float* edge_b1    = (const float*)d_in[7];   // [2048]
    const float* bias1      = (const float*)d_in[8];   // [64]
    const float* edge_W2    = (const float*)d_in[9];   // [5, 4096]
    const float* edge_b2    = (const float*)d_in[10];  // [4096]
    const float* bias2      = (const float*)d_in[11];  // [64]
    const float* ws_W       = (const float*)d_in[12];  // [64]
    const float* ws_b       = (const float*)d_in[13];  // [1]
    float* out = (float*)d_out;                        // [64, 128]

    float* P   = nullptr;
    float* agg = nullptr;
    cudaGetSymbolAddress((void**)&P,   g_P);
    cudaGetSymbolAddress((void**)&agg, g_agg);

    const int edge_blocks = (E0 * 32) / 256;           // 4096

    // Layer 1 (proj also initializes agg = bias1 + self-loop message)
    proj_kernel<DIN1, 0><<<296, 384>>>(node_feats, edge_W1, edge_b1, bias1, P, agg);
    edge_kernel<<<edge_blocks, 256>>>(P, edge_feats, src, dst, agg);

    // Layer 2 (relu applied to layer-1 agg on load)
    proj_kernel<DH, 1><<<148, 384>>>(agg, edge_W2, edge_b2, bias2, P, agg);
    edge_kernel<<<edge_blocks, 256>>>(P, edge_feats, src, dst, agg);

    // Pool + timestep + tanh(relu(.))
    pool_kernel<<<NB, 128>>>(agg, ws_W, ws_b, timestep, out);
}

// round 6
// speedup vs baseline: 1.2249x; 1.0075x over previous
#include <cuda_runtime.h>
#include <cuda_bf16.h>
#include <math_constants.h>

// Problem constants (fixed by the reference)
#define NNODES 8192
#define NB     64
#define E0     32768
#define DIN1   32
#define DH     64
#define BOND   5
// P layout: [N][6][64]  (k=0..4 bond projections, k=5 bias projection)
#define PSTRIDE (6*DH)   // 384

// Scratch (allocation-free rule: __device__ globals)
__device__ float g_P[NNODES * PSTRIDE];   // 12.6 MB, reused for layer 1 and 2
__device__ float g_agg[NNODES * DH];      // 2 MB, reused for layer 1 and 2

// Packed f32x2 FMA (Blackwell): acc.{lo,hi} += a.{lo,hi} * b.{lo,hi}
__device__ __forceinline__ void ffma2(unsigned long long& acc,
                                      unsigned long long a,
                                      unsigned long long b) {
    asm("fma.rn.f32x2 %0, %1, %2, %0;" : "+l"(acc) : "l"(a), "l"(b));
}
__device__ __forceinline__ unsigned long long pack2(float a, float b) {
    unsigned long long r;
    asm("mov.b64 %0, {%1, %2};" : "=l"(r) : "f"(a), "f"(b));
    return r;
}
__device__ __forceinline__ float unpack_sum(unsigned long long v) {
    float lo, hi;
    asm("mov.b64 {%0, %1}, %2;" : "=f"(lo), "=f"(hi) : "l"(v));
    return lo + hi;
}

// ---------------------------------------------------------------------------
// Projection: P[n, k*64+o] = sum_i x[n,i] * W_k[i,o]
//   W_k[i,o] = eW[k, i*64+o] for k<5, eb[i*64+o] for k==5
// Also fuses agg init: agg[n,o] = bias[o] + P_5[n,o]  (self-loop msg + bias)
// blockDim = 384 (thread owns one (k,o) column), 8 nodes per group,
// grid-stride over 1024 groups. Even/odd input dims packed into f32x2 lanes.
// ---------------------------------------------------------------------------
template<int DIN, int RELU_IN>
__global__ void __launch_bounds__(384) proj_kernel(
    const float* __restrict__ x,     // [N, DIN]
    const float* __restrict__ eW,    // [5, DIN*64]
    const float* __restrict__ eb,    // [DIN*64]
    const float* __restrict__ bias,  // [64]
    float* __restrict__ P,           // [N, 384]
    float* __restrict__ agg)         // [N, 64]
{
    const int tid = threadIdx.x;
    const int k = tid >> 6;
    const int o = tid & 63;

    // pre-packed weight column: wp[c] = (w[2c], w[2c+1])
    unsigned long long wp[DIN / 2];
    const float* wsrc = (k < 5) ? (eW + k * DIN * 64) : eb;
    #pragma unroll
    for (int c = 0; c < DIN / 2; c++)
        wp[c] = pack2(wsrc[(2 * c) * 64 + o], wsrc[(2 * c + 1) * 64 + o]);

    const float bo = bias[o];

    // 8 node rows of DIN floats (plain row layout; reads are warp-broadcast)
    __shared__ ulonglong2 xs[8][DIN / 4];

    for (int g = blockIdx.x; g < NNODES / 8; g += gridDim.x) {
        const int nbase = g * 8;

        // cooperative vectorized load (nodes are contiguous in memory)
        const float4* xg = reinterpret_cast<const float4*>(x + (size_t)nbase * DIN);
        if (tid < 2 * DIN) {
            float4 v = xg[tid];
            if (RELU_IN) {
                v.x = fmaxf(v.x, 0.f); v.y = fmaxf(v.y, 0.f);
                v.z = fmaxf(v.z, 0.f); v.w = fmaxf(v.w, 0.f);
            }
            reinterpret_cast<float4*>(xs)[tid] = v;
        }
        __syncthreads();

        unsigned long long acc[8];
        #pragma unroll
        for (int j = 0; j < 8; j++) acc[j] = 0ull;  // (0.f, 0.f)

        #pragma unroll
        for (int c = 0; c < DIN / 4; c++) {
            #pragma unroll
            for (int j = 0; j < 8; j++) {
                ulonglong2 v = xs[j][c];           // LDS.128 broadcast
                ffma2(acc[j], wp[2 * c],     v.x); // dims 4c, 4c+1
                ffma2(acc[j], wp[2 * c + 1], v.y); // dims 4c+2, 4c+3
            }
        }
        __syncthreads();

        #pragma unroll
        for (int j = 0; j < 8; j++) {
            const float r = unpack_sum(acc[j]);
            P[(size_t)(nbase + j) * PSTRIDE + tid] = r;
            if (k == 5)  // warp-uniform branch: fused agg init (bias + self-loop)
                agg[(size_t)(nbase + j) * DH + o] = bo + r;
        }
    }
}

// ---------------------------------------------------------------------------
// Edge scatter: one warp per edge; lane handles output pair (2*lane, 2*lane+1)
//   m = P_b[src] + sum_k ef[e,k] * P_k[src];  atomicAdd into agg[dst]
// ---------------------------------------------------------------------------
__global__ void __launch_bounds__(256) edge_kernel(
    const float* __restrict__ P,
    const float* __restrict__ ef,   // [E0, 5]
    const int*   __restrict__ src,
    const int*   __restrict__ dst,
    float* __restrict__ agg)
{
    const int e = (blockIdx.x * blockDim.x + threadIdx.x) >> 5;
    if (e >= E0) return;
    const int lane = threadIdx.x & 31;

    const int s = src[e];
    const int d = dst[e];
    const float f0 = ef[e * BOND + 0];
    const float f1 = ef[e * BOND + 1];
    const float f2 = ef[e * BOND + 2];
    const float f3 = ef[e * BOND + 3];
    const float f4 = ef[e * BOND + 4];

    const float2* p = reinterpret_cast<const float2*>(P + (size_t)s * PSTRIDE);
    const float2 pb = p[5 * 32 + lane];
    const float2 p0 = p[0 * 32 + lane];
    const float2 p1 = p[1 * 32 + lane];
    const float2 p2 = p[2 * 32 + lane];
    const float2 p3 = p[3 * 32 + lane];
    const float2 p4 = p[4 * 32 + lane];

    float mx = pb.x;
    mx = fmaf(f0, p0.x, mx); mx = fmaf(f1, p1.x, mx); mx = fmaf(f2, p2.x, mx);
    mx = fmaf(f3, p3.x, mx); mx = fmaf(f4, p4.x, mx);
    float my = pb.y;
    my = fmaf(f0, p0.y, my); my = fmaf(f1, p1.y, my); my = fmaf(f2, p2.y, my);
    my = fmaf(f3, p3.y, my); my = fmaf(f4, p4.y, my);

    float* a = agg + (size_t)d * DH + 2 * lane;
    atomicAdd(a,     mx);
    atomicAdd(a + 1, my);
}

// ---------------------------------------------------------------------------
// Pooling + timestep conditioning + final activation
// one block per graph (128 contiguous nodes), 128 threads
// ---------------------------------------------------------------------------
__global__ void __launch_bounds__(128) pool_kernel(
    const float* __restrict__ agg,   // [N, 64] (pre-relu)
    const float* __restrict__ wsW,   // [64]
    const float* __restrict__ wsb,   // [1]
    const float* __restrict__ tstep, // [B]
    float* __restrict__ out)         // [B, 128]
{
    __shared__ float hs[128][65];
    __shared__ float wv[128];
    __shared__ float gsum[64];
    __shared__ float gmax[64];

    const int g = blockIdx.x;
    const int t = threadIdx.x;
    const int base = g * 128;

    // coalesced load + relu
    for (int idx = t; idx < 128 * 64; idx += 128) {
        hs[idx >> 6][idx & 63] = fmaxf(agg[base * 64 + idx], 0.0f);
    }
    __syncthreads();

    // node weight w = sigmoid(h @ wsW + wsb)
    float acc = 0.f;
    #pragma unroll
    for (int c = 0; c < 64; c++) acc = fmaf(hs[t][c], wsW[c], acc);
    wv[t] = 1.0f / (1.0f + expf(-(acc + wsb[0])));
    __syncthreads();

    if (t < 64) {
        float s = 0.f, m = -CUDART_INF_F;
        #pragma unroll 4
        for (int r = 0; r < 128; r++) {
            const float h = hs[r][t];
            s = fmaf(h, wv[r], s);
            m = fmaxf(m, h);
        }
        gsum[t] = s;
        gmax[t] = m;
    }
    __syncthreads();

    const float ts = tstep[g];
    float v;
    if (t < 64) {
        const float inv = expf(-logf(10000.0f) * (2.0f * t) / 128.0f);
        v = gsum[t] + sinf(ts * inv);
    } else {
        const int j = t - 64;
        const float inv = expf(-logf(10000.0f) * (2.0f * j) / 128.0f);
        v = gmax[j] + cosf(ts * inv);
    }
    out[g * 128 + t] = tanhf(fmaxf(v, 0.0f));
}

// ---------------------------------------------------------------------------
extern "C" void kernel_launch(void* const* d_in, const int* in_sizes, int n_in,
                              void* d_out, int out_size)
{
    const float* node_feats = (const float*)d_in[0];   // [8192, 32]
    const float* edge_feats = (const float*)d_in[1];   // [32768, 5]
    const int*   src        = (const int*)  d_in[2];   // [32768]
    const int*   dst        = (const int*)  d_in[3];   // [32768]
    // d_in[4] = graph_ids (contiguous: g = n/128), unused
    const float* timestep   = (const float*)d_in[5];   // [64, 1]
    const float* edge_W1    = (const float*)d_in[6];   // [5, 2048]
    const float* edge_b1    = (const float*)d_in[7];   // [2048]
    const float* bias1      = (const float*)d_in[8];   // [64]
    const float* edge_W2    = (const float*)d_in[9];   // [5, 4096]
    const float* edge_b2    = (const float*)d_in[10];  // [4096]
    const float* bias2      = (const float*)d_in[11];  // [64]
    const float* ws_W       = (const float*)d_in[12];  // [64]
    const float* ws_b       = (const float*)d_in[13];  // [1]
    float* out = (float*)d_out;                        // [64, 128]

    float* P   = nullptr;
    float* agg = nullptr;
    cudaGetSymbolAddress((void**)&P,   g_P);
    cudaGetSymbolAddress((void**)&agg, g_agg);

    const int edge_blocks = (E0 * 32) / 256;           // 4096

    // Layer 1 (proj also initializes agg = bias1 + self-loop message)
    proj_kernel<DIN1, 0><<<296, 384>>>(node_feats, edge_W1, edge_b1, bias1, P, agg);
    edge_kernel<<<edge_blocks, 256>>>(P, edge_feats, src, dst, agg);

    // Layer 2 (relu applied to layer-1 agg on load)
    proj_kernel<DH, 1><<<148, 384>>>(agg, edge_W2, edge_b2, bias2, P, agg);
    edge_kernel<<<edge_blocks, 256>>>(P, edge_feats, src, dst, agg);

    // Pool + timestep + tanh(relu(.))
    pool_kernel<<<NB, 128>>>(agg, ws_W, ws_b, timestep, out);
}